// round 15
// baseline (speedup 1.0000x reference)
#include <cuda_runtime.h>
#include <cuda_fp16.h>
#include <math.h>
#include <stdint.h>

// ---------------- problem constants ----------------
#define BB   32
#define HH   28
#define WW   28
#define C1   64
#define DD   256
#define NHH  8
#define HDIM 32
#define SS   784            // HH*WW
#define TOT  (BB*C1*SS)     // 1,605,632
#define KSEL 803            // ceil(0.0005 * TOT)
#define MAXACT 832

#define SW_OFF   8192
#define SW_SIZE  (BB*SS*C1)
#define IDX_OFF  (SW_OFF + SW_SIZE)
#define OUT_FULL (IDX_OFF + BB*SS*2)

#define FSCALE (0.17677669529663689f * 1.4426950408889634f)  // 1/sqrt(32)*log2(e)

// ---------------- device scratch ----------------
__device__ __align__(16) float g_A[TOT];                 // conv output, layout [b][c][s]
__device__ __align__(16) float g_pe[SS*DD];
__device__ __align__(16) float g_qkv0[SS*3*DD];          // PE @ Wqkv^T + b (batch-invariant)
__device__ __align__(16) float g_dq[MAXACT*3*DD];        // sparse qkv deltas (compact)
__device__ __align__(16) float g_ctx[BB*SS*DD];
__device__ __align__(16) float g_U[MAXACT*DD];
__device__ __align__(16) float g_part[BB*8*DD];          // pool partials
__device__ __align__(16) unsigned g_cand[TOT];           // level-1 prefix candidates
__device__ int      g_didx[BB*SS];
__device__ unsigned g_hist1[2048];
__device__ unsigned g_hist2[2048];
__device__ unsigned g_hist3[1024];
__device__ int      g_nact;
__device__ int      g_ncand;

__device__ __forceinline__ void mma_f16(float c[4], const uint32_t a[4],
                                        uint32_t b0, uint32_t b1) {
    asm volatile("mma.sync.aligned.m16n8k16.row.col.f32.f16.f16.f32 "
                 "{%0,%1,%2,%3}, {%4,%5,%6,%7}, {%8,%9}, {%0,%1,%2,%3};"
                 : "+f"(c[0]), "+f"(c[1]), "+f"(c[2]), "+f"(c[3])
                 : "r"(a[0]), "r"(a[1]), "r"(a[2]), "r"(a[3]), "r"(b0), "r"(b1));
}

// Block-local radix scan over a completed global histogram.
__device__ __forceinline__ bool scan_bins(const unsigned* hist, int nbins, unsigned k,
                                          unsigned* part, unsigned* suf,
                                          unsigned& sel_out, unsigned& krem_out) {
    int t = threadIdx.x;
    int chunk = nbins / 256;
    unsigned loc[8];
    unsigned psum = 0;
    for (int i = 0; i < chunk; i++) { loc[i] = hist[t*chunk + i]; psum += loc[i]; }
    part[t] = psum; suf[t] = psum;
    __syncthreads();
    for (int off = 1; off < 256; off <<= 1) {
        unsigned v = suf[t];
        if (t + off < 256) v += suf[t + off];
        __syncthreads();
        suf[t] = v;
        __syncthreads();
    }
    unsigned total = suf[0];
    unsigned above = suf[t] - part[t];
    __syncthreads();
    if (total < k) return false;
    if (above < k && suf[t] >= k) {
        unsigned cum = above;
        for (int i = chunk - 1; i >= 0; i--) {
            cum += loc[i];
            if (cum >= k) {
                part[0] = (unsigned)(t*chunk + i);
                part[1] = k - (cum - loc[i]);
                break;
            }
        }
    }
    __syncthreads();
    sel_out = part[0]; krem_out = part[1];
    __syncthreads();
    return true;
}

// ---------------- fused conv(9x9)+relu+hist1 (A stored [b][c][s]) | PE ----------------
__global__ void k_conv_pe(const float* __restrict__ x, const float* __restrict__ cw) {
    int blk = blockIdx.x;
    int t = threadIdx.x;
    if (blk >= 256) {
        int s = blk - 256;
        int h = s / WW, w = s % WW;
        int i2 = t & ~1;
        float div = expf((float)i2 * (-logf(10000.0f) / (float)DD));
        float val = (t & 1) ? cosf((float)w * div) : sinf((float)h * div);
        g_pe[s * DD + t] = val;
        return;
    }
    __shared__ float xs[36][36];
    __shared__ float ws[8][81];
    __shared__ unsigned sh[2048];
    int b = blk >> 3, cg = blk & 7;
    for (int e = t; e < 36*36; e += 256) {
        int r = e / 36, c = e % 36;
        int hh = r - 4, ww = c - 4;
        xs[r][c] = (hh >= 0 && hh < HH && ww >= 0 && ww < WW) ? x[b*SS + hh*WW + ww] : 0.f;
    }
    for (int e = t; e < 8*81; e += 256) {
        int c8 = e / 81, k = e % 81;
        ws[c8][k] = cw[(cg*8 + c8)*81 + k];
    }
    for (int i = t; i < 2048; i += 256) sh[i] = 0;
    __syncthreads();
    for (int c8 = 0; c8 < 8; c8++) {
        for (int p = t; p < SS; p += 256) {
            int hh = p / WW, ww = p % WW;
            float acc = 0.f;
#pragma unroll
            for (int ky = 0; ky < 9; ky++)
#pragma unroll
                for (int kx = 0; kx < 9; kx++)
                    acc += xs[hh+ky][ww+kx] * ws[c8][ky*9 + kx];
            acc = fmaxf(acc, 0.f);
            g_A[((b*C1) + cg*8 + c8)*SS + p] = acc;
            unsigned u = __float_as_uint(acc);
            if (u) atomicAdd(&sh[u >> 21], 1u);
        }
    }
    __syncthreads();
    for (int i = t; i < 2048; i += 256) { unsigned v = sh[i]; if (v) atomicAdd(&g_hist1[i], v); }
}

// ---------------- hist2: scan1 prologue + level-2 histogram + candidate compaction ----------------
// uint4-vectorized scan of g_A (TOT is divisible by 4).
__global__ void k_hist2() {
    __shared__ unsigned sh[2048];
    __shared__ unsigned sp[256], ssu[256];
    int t = threadIdx.x;
    unsigned sel1, krem1;
    if (!scan_bins(g_hist1, 2048, KSEL, sp, ssu, sel1, krem1)) return;
    for (int i = t; i < 2048; i += 256) sh[i] = 0;
    __syncthreads();
    const uint4* a4 = (const uint4*)g_A;
    for (int idx = blockIdx.x*256 + t; idx < TOT/4; idx += gridDim.x*256) {
        uint4 u4 = a4[idx];
        unsigned uu[4] = {u4.x, u4.y, u4.z, u4.w};
#pragma unroll
        for (int j = 0; j < 4; j++) {
            unsigned u = uu[j];
            if (u && (u >> 21) == sel1) {
                atomicAdd(&sh[(u >> 10) & 0x7FF], 1u);
                int pos = atomicAdd(&g_ncand, 1);
                g_cand[pos] = u;
            }
        }
    }
    __syncthreads();
    for (int i = t; i < 2048; i += 256) { unsigned v = sh[i]; if (v) atomicAdd(&g_hist2[i], v); }
}

// ---------------- hist3: scan1+scan2 prologue + level-3 histogram over candidates ----------------
__global__ void k_hist3() {
    __shared__ unsigned sh[1024];
    __shared__ unsigned sp[256], ssu[256];
    int t = threadIdx.x;
    unsigned sel1, krem1, sel2, krem2;
    if (!scan_bins(g_hist1, 2048, KSEL, sp, ssu, sel1, krem1)) return;
    if (!scan_bins(g_hist2, 2048, krem1, sp, ssu, sel2, krem2)) return;
    int n = g_ncand;
    for (int i = t; i < 1024; i += 256) sh[i] = 0;
    __syncthreads();
    for (int i = blockIdx.x*256 + t; i < n; i += gridDim.x*256) {
        unsigned u = g_cand[i];
        if (((u >> 10) & 0x7FF) == sel2) atomicAdd(&sh[u & 0x3FF], 1u);
    }
    __syncthreads();
    for (int i = t; i < 1024; i += 256) { unsigned v = sh[i]; if (v) atomicAdd(&g_hist3[i], v); }
}

// ---------------- sparse: 3-scan prologue -> thresh; vectorized writes ----------------
__global__ void k_sparse(const float* __restrict__ emb, float* __restrict__ out, int full_out) {
    __shared__ unsigned sp[256], ssu[256];
    unsigned sel1, krem1, sel2, krem2, sel3, krem3;
    float thr = 0.f;
    if (scan_bins(g_hist1, 2048, KSEL, sp, ssu, sel1, krem1) &&
        scan_bins(g_hist2, 2048, krem1, sp, ssu, sel2, krem2) &&
        scan_bins(g_hist3, 1024, krem2, sp, ssu, sel3, krem3)) {
        unsigned prefix2 = (sel1 << 11) | sel2;
        thr = __uint_as_float((prefix2 << 10) | sel3);
    }
    int p = blockIdx.x*256 + threadIdx.x;
    if (p >= BB*SS) return;
    int b = p / SS, s = p % SS;
    float m1 = -INFINITY, m2 = -INFINITY;
    int i1 = 0, i2 = 0, cnt = 0;
    const float* ap = g_A + (size_t)b*C1*SS + s;
#pragma unroll 8
    for (int c = 0; c < C1; c++) {
        float a = ap[c*SS];
        float v = (a >= thr) ? a : 0.f;
        if (v > 0.f) cnt++;
        if (v > m1) { m2 = m1; i2 = i1; m1 = v; i1 = c; }
        else if (v > m2) { m2 = v; i2 = c; }
    }
    float wA = 0.f, wB = 0.f;
    if (cnt == 1) wA = 1.f;
    else if (cnt >= 2) {
        float e2 = expf(m2 - m1);
        float z = 1.f + e2;
        wA = 1.f / z; wB = e2 / z;
    }
    if (full_out) {
        float* sw = out + SW_OFF + (size_t)p*C1;
        float4 z4 = make_float4(0.f, 0.f, 0.f, 0.f);
#pragma unroll
        for (int c4 = 0; c4 < C1; c4 += 4) {
            float4 v4 = z4;
            if (i1 >= c4 && i1 < c4+4) (&v4.x)[i1 - c4] = wA;
            if (i2 >= c4 && i2 < c4+4) (&v4.x)[i2 - c4] = wB;
            *(float4*)&sw[c4] = v4;
        }
        out[IDX_OFF + p*2]     = (float)i1;
        out[IDX_OFF + p*2 + 1] = (float)i2;
    }
    int slotw = -1;
    if (cnt > 0) {
        int slot = atomicAdd(&g_nact, 1);
        if (slot < MAXACT) {
            slotw = slot;
            float w2v = (cnt >= 2) ? wB : 0.f;
            float* up = g_U + (size_t)slot*DD;
            const float* e1p = emb + i1*DD;
            const float* e2p = emb + i2*DD;
#pragma unroll 4
            for (int d4 = 0; d4 < DD; d4 += 4) {
                float4 e1 = *(const float4*)&e1p[d4];
                float4 e2 = *(const float4*)&e2p[d4];
                float4 u4;
                u4.x = wA*e1.x + w2v*e2.x;
                u4.y = wA*e1.y + w2v*e2.y;
                u4.z = wA*e1.z + w2v*e2.z;
                u4.w = wA*e1.w + w2v*e2.w;
                *(float4*)&up[d4] = u4;
            }
        }
    }
    g_didx[p] = slotw;
}

// ---------------- fused qkv0 (x<13) + delta (x>=13) ----------------
__global__ void k_qkvdelta(const float* __restrict__ Wq, const float* __restrict__ bias) {
    __shared__ float As[16][68];
    __shared__ float Bs[16][68];
    int tx = threadIdx.x % 16, ty = threadIdx.x / 16;
    int bx = blockIdx.x;
    int is_delta = (bx >= 13);
    int m0 = (is_delta ? (bx - 13) : bx) * 64;
    int n0 = blockIdx.y*64;
    int mlim;
    const float* Asrc;
    if (is_delta) {
        int nact = g_nact; if (nact > MAXACT) nact = MAXACT;
        if (m0 >= nact) return;
        mlim = nact;
        Asrc = g_U;
    } else {
        mlim = SS;
        Asrc = g_pe;
    }
    float acc[4][4] = {};
    int lr = threadIdx.x / 4;
    int lk = (threadIdx.x % 4) * 4;
    for (int k0 = 0; k0 < DD; k0 += 16) {
        float4 av = (m0 + lr < mlim) ? *(const float4*)&Asrc[(size_t)(m0+lr)*DD + k0 + lk] : make_float4(0,0,0,0);
        float4 bv = *(const float4*)&Wq[(n0+lr)*DD + k0 + lk];
        __syncthreads();
        As[lk+0][lr] = av.x; As[lk+1][lr] = av.y; As[lk+2][lr] = av.z; As[lk+3][lr] = av.w;
        Bs[lk+0][lr] = bv.x; Bs[lk+1][lr] = bv.y; Bs[lk+2][lr] = bv.z; Bs[lk+3][lr] = bv.w;
        __syncthreads();
#pragma unroll
        for (int kk = 0; kk < 16; kk++) {
            float4 a4 = *(const float4*)&As[kk][ty*4];
            float4 b4 = *(const float4*)&Bs[kk][tx*4];
            float sa[4] = {a4.x, a4.y, a4.z, a4.w};
            float sb[4] = {b4.x, b4.y, b4.z, b4.w};
#pragma unroll
            for (int i = 0; i < 4; i++)
#pragma unroll
                for (int j = 0; j < 4; j++)
                    acc[i][j] += sa[i]*sb[j];
        }
    }
#pragma unroll
    for (int i = 0; i < 4; i++) {
        int m = m0 + ty*4 + i;
        if (m < mlim) {
            if (is_delta) {
                float* dst = g_dq + (size_t)m*768 + n0 + tx*4;
#pragma unroll
                for (int j = 0; j < 4; j++) dst[j] = acc[i][j];
            } else {
#pragma unroll
                for (int j = 0; j < 4; j++) {
                    int n = n0 + tx*4 + j;
                    g_qkv0[m*768 + n] = acc[i][j] + bias[n];
                }
            }
        }
    }
}

// ---------------- tensor-core flash attention (fp16 m16n8k16, FM=64, Q/P union, occ 6) ----------------
#define FM 64
#define FN 64
__global__ __launch_bounds__(128, 6) void k_flash() {
    __shared__ __align__(16) float   QP[FM][36];     // Q staging (fp32), then P (half2 view)
    __shared__ __align__(16) __half2 Kh2[FN][20];    // K hi
    __shared__ __align__(16) __half2 Kl2[FN][20];    // K lo
    __shared__ __align__(16) __half  Vst[32][72];    // V^T [dim][key]
    __half2* Ps2 = (__half2*)&QP[0][0];              // [r][c] -> Ps2[r*36 + c]
    int b = blockIdx.z, h = blockIdx.y;
    int q0 = blockIdx.x * FM;
    int t = threadIdx.x;
    int w = t >> 5, lane = t & 31;
    int l4 = lane >> 2, lm = lane & 3;

    const int* didx = g_didx + b*SS;

    for (int f = t; f < FM*8; f += 128) {
        int r = f >> 3, c4 = (f & 7) * 4;
        int gr = q0 + r;
        float4 v = make_float4(0.f,0.f,0.f,0.f);
        if (gr < SS) {
            v = *(const float4*)(g_qkv0 + (size_t)gr*768 + h*HDIM + c4);
            int sl = didx[gr];
            if (sl >= 0) {
                float4 d = *(const float4*)(g_dq + (size_t)sl*768 + h*HDIM + c4);
                v.x += d.x; v.y += d.y; v.z += d.z; v.w += d.w;
            }
        }
        QP[r][c4+0] = v.x*FSCALE; QP[r][c4+1] = v.y*FSCALE;
        QP[r][c4+2] = v.z*FSCALE; QP[r][c4+3] = v.w*FSCALE;
    }
    __syncthreads();

    int r0 = w * 16;
    uint32_t aqh[2][4], aql[2][4];
#pragma unroll
    for (int ks = 0; ks < 2; ks++) {
        int kk = ks*16;
        float p0[4], p1[4];
        p0[0] = QP[r0+l4  ][kk+2*lm  ];  p1[0] = QP[r0+l4  ][kk+2*lm+1];
        p0[1] = QP[r0+l4+8][kk+2*lm  ];  p1[1] = QP[r0+l4+8][kk+2*lm+1];
        p0[2] = QP[r0+l4  ][kk+2*lm+8];  p1[2] = QP[r0+l4  ][kk+2*lm+9];
        p0[3] = QP[r0+l4+8][kk+2*lm+8];  p1[3] = QP[r0+l4+8][kk+2*lm+9];
#pragma unroll
        for (int j = 0; j < 4; j++) {
            __half h0 = __float2half_rn(p0[j]);
            __half h1 = __float2half_rn(p1[j]);
            __half l0 = __float2half_rn(p0[j] - __half2float(h0));
            __half l1 = __float2half_rn(p1[j] - __half2float(h1));
            __half2 hh = __halves2half2(h0, h1);
            __half2 ll = __halves2half2(l0, l1);
            aqh[ks][j] = *(uint32_t*)&hh;
            aql[ks][j] = *(uint32_t*)&ll;
        }
    }
    __syncwarp();   // warp-private rows of QP reused as P from here

    float m_i[2], l_i[2], o[4][4];
#pragma unroll
    for (int hf = 0; hf < 2; hf++) { m_i[hf] = -INFINITY; l_i[hf] = 0.f; }
#pragma unroll
    for (int nt = 0; nt < 4; nt++)
#pragma unroll
        for (int c = 0; c < 4; c++) o[nt][c] = 0.f;

    for (int k0 = 0; k0 < SS; k0 += FN) {
        __syncthreads();
        for (int f = t; f < FN*8; f += 128) {
            int r = f >> 3, c4 = (f & 7) * 4;
            int gr = k0 + r;
            float4 kv = make_float4(0.f,0.f,0.f,0.f), vv = make_float4(0.f,0.f,0.f,0.f);
            if (gr < SS) {
                const float* base = g_qkv0 + (size_t)gr*768 + h*HDIM + c4;
                kv = *(const float4*)(base + DD);
                vv = *(const float4*)(base + 2*DD);
                int sl = didx[gr];
                if (sl >= 0) {
                    const float* dbase = g_dq + (size_t)sl*768 + h*HDIM + c4;
                    float4 dk = *(const float4*)(dbase + DD);
                    float4 dv = *(const float4*)(dbase + 2*DD);
                    kv.x += dk.x; kv.y += dk.y; kv.z += dk.z; kv.w += dk.w;
                    vv.x += dv.x; vv.y += dv.y; vv.z += dv.z; vv.w += dv.w;
                }
            }
            __half h0 = __float2half_rn(kv.x), h1 = __float2half_rn(kv.y);
            __half h2 = __float2half_rn(kv.z), h3 = __float2half_rn(kv.w);
            Kh2[r][c4/2  ] = __halves2half2(h0, h1);
            Kh2[r][c4/2+1] = __halves2half2(h2, h3);
            Kl2[r][c4/2  ] = __halves2half2(__float2half_rn(kv.x - __half2float(h0)),
                                            __float2half_rn(kv.y - __half2float(h1)));
            Kl2[r][c4/2+1] = __halves2half2(__float2half_rn(kv.z - __half2float(h2)),
                                            __float2half_rn(kv.w - __half2float(h3)));
            Vst[c4+0][r] = __float2half_rn(vv.x);
            Vst[c4+1][r] = __float2half_rn(vv.y);
            Vst[c4+2][r] = __float2half_rn(vv.z);
            Vst[c4+3][r] = __float2half_rn(vv.w);
        }
        __syncthreads();

        float c[8][4];
#pragma unroll
        for (int nt = 0; nt < 8; nt++) {
            c[nt][0] = c[nt][1] = c[nt][2] = c[nt][3] = 0.f;
            int kr = nt*8 + l4;
#pragma unroll
            for (int ks = 0; ks < 2; ks++) {
                int kk2 = ks*8;
                uint32_t bh0 = *(const uint32_t*)&Kh2[kr][kk2+lm  ];
                uint32_t bh1 = *(const uint32_t*)&Kh2[kr][kk2+lm+4];
                uint32_t bl0 = *(const uint32_t*)&Kl2[kr][kk2+lm  ];
                uint32_t bl1 = *(const uint32_t*)&Kl2[kr][kk2+lm+4];
                mma_f16(c[nt], aqh[ks], bl0, bl1);   // Qh*Kl
                mma_f16(c[nt], aql[ks], bh0, bh1);   // Ql*Kh
                mma_f16(c[nt], aqh[ks], bh0, bh1);   // Qh*Kh (dominant last)
            }
        }
        if (k0 + FN > SS) {
#pragma unroll
            for (int nt = 0; nt < 8; nt++) {
                int j0 = k0 + nt*8 + lm*2;
                if (j0 >= SS) { c[nt][0] = c[nt][1] = c[nt][2] = c[nt][3] = -1e30f; }
            }
        }
#pragma unroll
        for (int hf = 0; hf < 2; hf++) {
            float rm = -INFINITY;
#pragma unroll
            for (int nt = 0; nt < 8; nt++)
                rm = fmaxf(rm, fmaxf(c[nt][2*hf], c[nt][2*hf+1]));
            rm = fmaxf(rm, __shfl_xor_sync(0xffffffffu, rm, 1));
            rm = fmaxf(rm, __shfl_xor_sync(0xffffffffu, rm, 2));
            float mn = fmaxf(m_i[hf], rm);
            float alpha = exp2f(m_i[hf] - mn);
            float rs = 0.f;
#pragma unroll
            for (int nt = 0; nt < 8; nt++) {
                float p0 = exp2f(c[nt][2*hf]   - mn);
                float p1 = exp2f(c[nt][2*hf+1] - mn);
                c[nt][2*hf] = p0; c[nt][2*hf+1] = p1;
                rs += p0 + p1;
            }
            rs += __shfl_xor_sync(0xffffffffu, rs, 1);
            rs += __shfl_xor_sync(0xffffffffu, rs, 2);
            l_i[hf] = l_i[hf]*alpha + rs;
            m_i[hf] = mn;
#pragma unroll
            for (int nt = 0; nt < 4; nt++) {
                o[nt][2*hf]   *= alpha;
                o[nt][2*hf+1] *= alpha;
            }
        }
#pragma unroll
        for (int nt = 0; nt < 8; nt++) {
            Ps2[(r0+l4  )*36 + nt*4+lm] = __floats2half2_rn(c[nt][0], c[nt][1]);
            Ps2[(r0+l4+8)*36 + nt*4+lm] = __floats2half2_rn(c[nt][2], c[nt][3]);
        }
        __syncwarp();
#pragma unroll
        for (int ks = 0; ks < 4; ks++) {
            int kk2 = ks*8;
            int kk  = ks*16;
            uint32_t a[4];
            a[0] = *(const uint32_t*)&Ps2[(r0+l4  )*36 + kk2+lm  ];
            a[1] = *(const uint32_t*)&Ps2[(r0+l4+8)*36 + kk2+lm  ];
            a[2] = *(const uint32_t*)&Ps2[(r0+l4  )*36 + kk2+lm+4];
            a[3] = *(const uint32_t*)&Ps2[(r0+l4+8)*36 + kk2+lm+4];
#pragma unroll
            for (int nt = 0; nt < 4; nt++) {
                uint32_t b0 = *(const uint32_t*)&Vst[nt*8+l4][kk + 2*lm    ];
                uint32_t b1 = *(const uint32_t*)&Vst[nt*8+l4][kk + 2*lm + 8];
                mma_f16(o[nt], a, b0, b1);
            }
        }
        __syncwarp();
    }

#pragma unroll
    for (int hf = 0; hf < 2; hf++) {
        int gr = q0 + r0 + l4 + hf*8;
        if (gr < SS) {
            float inv = 1.f / l_i[hf];
#pragma unroll
            for (int nt = 0; nt < 4; nt++) {
                float2 v = make_float2(o[nt][2*hf]*inv, o[nt][2*hf+1]*inv);
                *(float2*)&g_ctx[(size_t)(b*SS+gr)*DD + h*HDIM + nt*8 + lm*2] = v;
            }
        }
    }
}

// ---------------- pool stage 1: partial sums over 98-row stripes ----------------
__global__ void k_pool1() {
    int b = blockIdx.x, ch = blockIdx.y, t = threadIdx.x;
    float s = 0.f;
    const float* base = g_ctx + ((size_t)b*SS + ch*98)*DD + t;
#pragma unroll 7
    for (int si = 0; si < 98; si++) s += base[(size_t)si*DD];
    g_part[((size_t)b*8 + ch)*DD + t] = s;
}

// ---------------- pool stage 2: fold partials + out-proj + state reset ----------------
__global__ void k_pool2(const float* __restrict__ Wo, const float* __restrict__ bo,
                        float* __restrict__ out) {
    __shared__ float mean[DD];
    int b = blockIdx.x, t = threadIdx.x;
    int gid = b*256 + t;
    if (gid < 2048) g_hist1[gid] = 0;
    else if (gid < 4096) g_hist2[gid - 2048] = 0;
    else if (gid < 5120) g_hist3[gid - 4096] = 0;
    else if (gid == 5120) g_nact = 0;
    else if (gid == 5121) g_ncand = 0;

    float s = 0.f;
    const float* pb = g_part + (size_t)b*8*DD + t;
#pragma unroll
    for (int ch = 0; ch < 8; ch++) s += pb[ch*DD];
    mean[t] = s * (1.f / (float)SS);
    __syncthreads();
    float acc = bo[t];
    const float* wrow = Wo + t*DD;
#pragma unroll 8
    for (int d = 0; d < DD; d++) acc += mean[d]*wrow[d];
    out[b*DD + t] = acc;
}

// ---------------- launch ----------------
extern "C" void kernel_launch(void* const* d_in, const int* in_sizes, int n_in,
                              void* d_out, int out_size) {
    const float* x    = (const float*)d_in[0];
    const float* cw   = (const float*)d_in[1];
    const float* emb  = (const float*)d_in[2];
    const float* ipw  = (const float*)d_in[3];
    const float* ipb  = (const float*)d_in[4];
    const float* opw  = (const float*)d_in[5];
    const float* opb  = (const float*)d_in[6];
    float* out = (float*)d_out;
    int full_out = (out_size >= OUT_FULL) ? 1 : 0;

    k_conv_pe<<<1040, 256>>>(x, cw);
    k_hist2<<<256, 256>>>();
    k_hist3<<<16, 256>>>();
    k_sparse<<<(BB*SS + 255)/256, 256>>>(emb, out, full_out);
    k_qkvdelta<<<dim3(26, 12), 256>>>(ipw, ipb);
    k_flash<<<dim3((SS + FM - 1)/FM, NHH, BB), 128>>>();
    k_pool1<<<dim3(BB, 8), 256>>>();
    k_pool2<<<BB, 256>>>(opw, opb, out);
}

// round 16
// speedup vs baseline: 1.0190x; 1.0190x over previous
#include <cuda_runtime.h>
#include <cuda_fp16.h>
#include <math.h>
#include <stdint.h>

// ---------------- problem constants ----------------
#define BB   32
#define HH   28
#define WW   28
#define C1   64
#define DD   256
#define NHH  8
#define HDIM 32
#define SS   784            // HH*WW
#define TOT  (BB*C1*SS)     // 1,605,632
#define KSEL 803            // ceil(0.0005 * TOT)
#define MAXACT 832

#define SW_OFF   8192
#define SW_SIZE  (BB*SS*C1)
#define IDX_OFF  (SW_OFF + SW_SIZE)
#define OUT_FULL (IDX_OFF + BB*SS*2)

#define FSCALE (0.17677669529663689f * 1.4426950408889634f)  // 1/sqrt(32)*log2(e)

// ---------------- device scratch ----------------
__device__ __align__(16) float g_A[TOT];                 // conv output, layout [b][c][s]
__device__ __align__(16) float g_pe[SS*DD];
__device__ __align__(16) float g_qkv0[SS*3*DD];          // PE @ Wqkv^T + b (batch-invariant)
__device__ __align__(16) float g_dq[MAXACT*3*DD];        // sparse qkv deltas (compact)
__device__ __align__(16) float g_ctx[BB*SS*DD];
__device__ __align__(16) float g_U[MAXACT*DD];
__device__ __align__(16) float g_part[BB*8*DD];          // pool partials
__device__ __align__(16) unsigned g_cand[TOT];           // level-1 prefix candidates
__device__ int      g_didx[BB*SS];
__device__ unsigned g_hist1[2048];
__device__ unsigned g_hist2[2048];
__device__ unsigned g_hist3[1024];
__device__ int      g_nact;
__device__ int      g_ncand;

__device__ __forceinline__ void mma_f16(float c[4], const uint32_t a[4],
                                        uint32_t b0, uint32_t b1) {
    asm volatile("mma.sync.aligned.m16n8k16.row.col.f32.f16.f16.f32 "
                 "{%0,%1,%2,%3}, {%4,%5,%6,%7}, {%8,%9}, {%0,%1,%2,%3};"
                 : "+f"(c[0]), "+f"(c[1]), "+f"(c[2]), "+f"(c[3])
                 : "r"(a[0]), "r"(a[1]), "r"(a[2]), "r"(a[3]), "r"(b0), "r"(b1));
}

// Block-local radix scan over a completed global histogram.
__device__ __forceinline__ bool scan_bins(const unsigned* hist, int nbins, unsigned k,
                                          unsigned* part, unsigned* suf,
                                          unsigned& sel_out, unsigned& krem_out) {
    int t = threadIdx.x;
    int chunk = nbins / 256;
    unsigned loc[8];
    unsigned psum = 0;
    for (int i = 0; i < chunk; i++) { loc[i] = hist[t*chunk + i]; psum += loc[i]; }
    part[t] = psum; suf[t] = psum;
    __syncthreads();
    for (int off = 1; off < 256; off <<= 1) {
        unsigned v = suf[t];
        if (t + off < 256) v += suf[t + off];
        __syncthreads();
        suf[t] = v;
        __syncthreads();
    }
    unsigned total = suf[0];
    unsigned above = suf[t] - part[t];
    __syncthreads();
    if (total < k) return false;
    if (above < k && suf[t] >= k) {
        unsigned cum = above;
        for (int i = chunk - 1; i >= 0; i--) {
            cum += loc[i];
            if (cum >= k) {
                part[0] = (unsigned)(t*chunk + i);
                part[1] = k - (cum - loc[i]);
                break;
            }
        }
    }
    __syncthreads();
    sel_out = part[0]; krem_out = part[1];
    __syncthreads();
    return true;
}

// ---------------- fused conv(9x9)+relu+hist1 (A stored [b][c][s]) | PE ----------------
__global__ void k_conv_pe(const float* __restrict__ x, const float* __restrict__ cw) {
    int blk = blockIdx.x;
    int t = threadIdx.x;
    if (blk >= 256) {
        int s = blk - 256;
        int h = s / WW, w = s % WW;
        int i2 = t & ~1;
        float div = expf((float)i2 * (-logf(10000.0f) / (float)DD));
        float val = (t & 1) ? cosf((float)w * div) : sinf((float)h * div);
        g_pe[s * DD + t] = val;
        return;
    }
    __shared__ float xs[36][36];
    __shared__ float ws[8][81];
    __shared__ unsigned sh[2048];
    int b = blk >> 3, cg = blk & 7;
    for (int e = t; e < 36*36; e += 256) {
        int r = e / 36, c = e % 36;
        int hh = r - 4, ww = c - 4;
        xs[r][c] = (hh >= 0 && hh < HH && ww >= 0 && ww < WW) ? x[b*SS + hh*WW + ww] : 0.f;
    }
    for (int e = t; e < 8*81; e += 256) {
        int c8 = e / 81, k = e % 81;
        ws[c8][k] = cw[(cg*8 + c8)*81 + k];
    }
    for (int i = t; i < 2048; i += 256) sh[i] = 0;
    __syncthreads();
    for (int c8 = 0; c8 < 8; c8++) {
        for (int p = t; p < SS; p += 256) {
            int hh = p / WW, ww = p % WW;
            float acc = 0.f;
#pragma unroll
            for (int ky = 0; ky < 9; ky++)
#pragma unroll
                for (int kx = 0; kx < 9; kx++)
                    acc += xs[hh+ky][ww+kx] * ws[c8][ky*9 + kx];
            acc = fmaxf(acc, 0.f);
            g_A[((b*C1) + cg*8 + c8)*SS + p] = acc;
            unsigned u = __float_as_uint(acc);
            if (u) atomicAdd(&sh[u >> 21], 1u);
        }
    }
    __syncthreads();
    for (int i = t; i < 2048; i += 256) { unsigned v = sh[i]; if (v) atomicAdd(&g_hist1[i], v); }
}

// ---------------- hist2: scan1 prologue + level-2 histogram + candidate compaction ----------------
// uint4-vectorized scan of g_A (TOT divisible by 4).
__global__ void k_hist2() {
    __shared__ unsigned sh[2048];
    __shared__ unsigned sp[256], ssu[256];
    int t = threadIdx.x;
    unsigned sel1, krem1;
    if (!scan_bins(g_hist1, 2048, KSEL, sp, ssu, sel1, krem1)) return;
    for (int i = t; i < 2048; i += 256) sh[i] = 0;
    __syncthreads();
    const uint4* a4 = (const uint4*)g_A;
    for (int idx = blockIdx.x*256 + t; idx < TOT/4; idx += gridDim.x*256) {
        uint4 u4 = a4[idx];
        unsigned uu[4] = {u4.x, u4.y, u4.z, u4.w};
#pragma unroll
        for (int j = 0; j < 4; j++) {
            unsigned u = uu[j];
            if (u && (u >> 21) == sel1) {
                atomicAdd(&sh[(u >> 10) & 0x7FF], 1u);
                int pos = atomicAdd(&g_ncand, 1);
                g_cand[pos] = u;
            }
        }
    }
    __syncthreads();
    for (int i = t; i < 2048; i += 256) { unsigned v = sh[i]; if (v) atomicAdd(&g_hist2[i], v); }
}

// ---------------- hist3: scan1+scan2 prologue + level-3 histogram over candidates ----------------
__global__ void k_hist3() {
    __shared__ unsigned sh[1024];
    __shared__ unsigned sp[256], ssu[256];
    int t = threadIdx.x;
    unsigned sel1, krem1, sel2, krem2;
    if (!scan_bins(g_hist1, 2048, KSEL, sp, ssu, sel1, krem1)) return;
    if (!scan_bins(g_hist2, 2048, krem1, sp, ssu, sel2, krem2)) return;
    int n = g_ncand;
    for (int i = t; i < 1024; i += 256) sh[i] = 0;
    __syncthreads();
    for (int i = blockIdx.x*256 + t; i < n; i += gridDim.x*256) {
        unsigned u = g_cand[i];
        if (((u >> 10) & 0x7FF) == sel2) atomicAdd(&sh[u & 0x3FF], 1u);
    }
    __syncthreads();
    for (int i = t; i < 1024; i += 256) { unsigned v = sh[i]; if (v) atomicAdd(&g_hist3[i], v); }
}

// ---------------- sparse: 3-scan prologue -> thresh; vectorized writes ----------------
__global__ void k_sparse(const float* __restrict__ emb, float* __restrict__ out, int full_out) {
    __shared__ unsigned sp[256], ssu[256];
    unsigned sel1, krem1, sel2, krem2, sel3, krem3;
    float thr = 0.f;
    if (scan_bins(g_hist1, 2048, KSEL, sp, ssu, sel1, krem1) &&
        scan_bins(g_hist2, 2048, krem1, sp, ssu, sel2, krem2) &&
        scan_bins(g_hist3, 1024, krem2, sp, ssu, sel3, krem3)) {
        unsigned prefix2 = (sel1 << 11) | sel2;
        thr = __uint_as_float((prefix2 << 10) | sel3);
    }
    int p = blockIdx.x*256 + threadIdx.x;
    if (p >= BB*SS) return;
    int b = p / SS, s = p % SS;
    float m1 = -INFINITY, m2 = -INFINITY;
    int i1 = 0, i2 = 0, cnt = 0;
    const float* ap = g_A + (size_t)b*C1*SS + s;
#pragma unroll 16
    for (int c = 0; c < C1; c++) {
        float a = ap[c*SS];
        float v = (a >= thr) ? a : 0.f;
        if (v > 0.f) cnt++;
        if (v > m1) { m2 = m1; i2 = i1; m1 = v; i1 = c; }
        else if (v > m2) { m2 = v; i2 = c; }
    }
    float wA = 0.f, wB = 0.f;
    if (cnt == 1) wA = 1.f;
    else if (cnt >= 2) {
        float e2 = expf(m2 - m1);
        float z = 1.f + e2;
        wA = 1.f / z; wB = e2 / z;
    }
    if (full_out) {
        float* sw = out + SW_OFF + (size_t)p*C1;
        float4 z4 = make_float4(0.f, 0.f, 0.f, 0.f);
#pragma unroll
        for (int c4 = 0; c4 < C1; c4 += 4) {
            float4 v4 = z4;
            if (i1 >= c4 && i1 < c4+4) (&v4.x)[i1 - c4] = wA;
            if (i2 >= c4 && i2 < c4+4) (&v4.x)[i2 - c4] = wB;
            *(float4*)&sw[c4] = v4;
        }
        out[IDX_OFF + p*2]     = (float)i1;
        out[IDX_OFF + p*2 + 1] = (float)i2;
    }
    int slotw = -1;
    if (cnt > 0) {
        int slot = atomicAdd(&g_nact, 1);
        if (slot < MAXACT) {
            slotw = slot;
            float w2v = (cnt >= 2) ? wB : 0.f;
            float* up = g_U + (size_t)slot*DD;
            const float* e1p = emb + i1*DD;
            const float* e2p = emb + i2*DD;
#pragma unroll 4
            for (int d4 = 0; d4 < DD; d4 += 4) {
                float4 e1 = *(const float4*)&e1p[d4];
                float4 e2 = *(const float4*)&e2p[d4];
                float4 u4;
                u4.x = wA*e1.x + w2v*e2.x;
                u4.y = wA*e1.y + w2v*e2.y;
                u4.z = wA*e1.z + w2v*e2.z;
                u4.w = wA*e1.w + w2v*e2.w;
                *(float4*)&up[d4] = u4;
            }
        }
    }
    g_didx[p] = slotw;
}

// ---------------- fused qkv0 (x<13) + delta (x>=13) ----------------
__global__ void k_qkvdelta(const float* __restrict__ Wq, const float* __restrict__ bias) {
    __shared__ float As[16][68];
    __shared__ float Bs[16][68];
    int tx = threadIdx.x % 16, ty = threadIdx.x / 16;
    int bx = blockIdx.x;
    int is_delta = (bx >= 13);
    int m0 = (is_delta ? (bx - 13) : bx) * 64;
    int n0 = blockIdx.y*64;
    int mlim;
    const float* Asrc;
    if (is_delta) {
        int nact = g_nact; if (nact > MAXACT) nact = MAXACT;
        if (m0 >= nact) return;
        mlim = nact;
        Asrc = g_U;
    } else {
        mlim = SS;
        Asrc = g_pe;
    }
    float acc[4][4] = {};
    int lr = threadIdx.x / 4;
    int lk = (threadIdx.x % 4) * 4;
    for (int k0 = 0; k0 < DD; k0 += 16) {
        float4 av = (m0 + lr < mlim) ? *(const float4*)&Asrc[(size_t)(m0+lr)*DD + k0 + lk] : make_float4(0,0,0,0);
        float4 bv = *(const float4*)&Wq[(n0+lr)*DD + k0 + lk];
        __syncthreads();
        As[lk+0][lr] = av.x; As[lk+1][lr] = av.y; As[lk+2][lr] = av.z; As[lk+3][lr] = av.w;
        Bs[lk+0][lr] = bv.x; Bs[lk+1][lr] = bv.y; Bs[lk+2][lr] = bv.z; Bs[lk+3][lr] = bv.w;
        __syncthreads();
#pragma unroll
        for (int kk = 0; kk < 16; kk++) {
            float4 a4 = *(const float4*)&As[kk][ty*4];
            float4 b4 = *(const float4*)&Bs[kk][tx*4];
            float sa[4] = {a4.x, a4.y, a4.z, a4.w};
            float sb[4] = {b4.x, b4.y, b4.z, b4.w};
#pragma unroll
            for (int i = 0; i < 4; i++)
#pragma unroll
                for (int j = 0; j < 4; j++)
                    acc[i][j] += sa[i]*sb[j];
        }
    }
#pragma unroll
    for (int i = 0; i < 4; i++) {
        int m = m0 + ty*4 + i;
        if (m < mlim) {
            if (is_delta) {
                float* dst = g_dq + (size_t)m*768 + n0 + tx*4;
#pragma unroll
                for (int j = 0; j < 4; j++) dst[j] = acc[i][j];
            } else {
#pragma unroll
                for (int j = 0; j < 4; j++) {
                    int n = n0 + tx*4 + j;
                    g_qkv0[m*768 + n] = acc[i][j] + bias[n];
                }
            }
        }
    }
}

// ---------------- tensor-core flash attention (fp16 m16n8k16, FM=64, R14 config) ----------------
#define FM 64
#define FN 64
__global__ __launch_bounds__(128, 5) void k_flash() {
    __shared__ __align__(16) float   Qs[FM][36];     // fp32 Q staging
    __shared__ __align__(16) __half2 Ps2[FM][36];    // P tiles (per-warp rows)
    __shared__ __align__(16) __half2 Kh2[FN][20];    // K hi
    __shared__ __align__(16) __half2 Kl2[FN][20];    // K lo
    __shared__ __align__(16) __half  Vst[32][72];    // V^T [dim][key]
    int b = blockIdx.z, h = blockIdx.y;
    int q0 = blockIdx.x * FM;
    int t = threadIdx.x;
    int w = t >> 5, lane = t & 31;
    int l4 = lane >> 2, lm = lane & 3;

    const int* didx = g_didx + b*SS;

    for (int f = t; f < FM*8; f += 128) {
        int r = f >> 3, c4 = (f & 7) * 4;
        int gr = q0 + r;
        float4 v = make_float4(0.f,0.f,0.f,0.f);
        if (gr < SS) {
            v = *(const float4*)(g_qkv0 + (size_t)gr*768 + h*HDIM + c4);
            int sl = didx[gr];
            if (sl >= 0) {
                float4 d = *(const float4*)(g_dq + (size_t)sl*768 + h*HDIM + c4);
                v.x += d.x; v.y += d.y; v.z += d.z; v.w += d.w;
            }
        }
        Qs[r][c4+0] = v.x*FSCALE; Qs[r][c4+1] = v.y*FSCALE;
        Qs[r][c4+2] = v.z*FSCALE; Qs[r][c4+3] = v.w*FSCALE;
    }
    __syncthreads();

    int r0 = w * 16;
    uint32_t aqh[2][4], aql[2][4];
#pragma unroll
    for (int ks = 0; ks < 2; ks++) {
        int kk = ks*16;
        float p0[4], p1[4];
        p0[0] = Qs[r0+l4  ][kk+2*lm  ];  p1[0] = Qs[r0+l4  ][kk+2*lm+1];
        p0[1] = Qs[r0+l4+8][kk+2*lm  ];  p1[1] = Qs[r0+l4+8][kk+2*lm+1];
        p0[2] = Qs[r0+l4  ][kk+2*lm+8];  p1[2] = Qs[r0+l4  ][kk+2*lm+9];
        p0[3] = Qs[r0+l4+8][kk+2*lm+8];  p1[3] = Qs[r0+l4+8][kk+2*lm+9];
#pragma unroll
        for (int j = 0; j < 4; j++) {
            __half h0 = __float2half_rn(p0[j]);
            __half h1 = __float2half_rn(p1[j]);
            __half l0 = __float2half_rn(p0[j] - __half2float(h0));
            __half l1 = __float2half_rn(p1[j] - __half2float(h1));
            __half2 hh = __halves2half2(h0, h1);
            __half2 ll = __halves2half2(l0, l1);
            aqh[ks][j] = *(uint32_t*)&hh;
            aql[ks][j] = *(uint32_t*)&ll;
        }
    }

    float m_i[2], l_i[2], o[4][4];
#pragma unroll
    for (int hf = 0; hf < 2; hf++) { m_i[hf] = -INFINITY; l_i[hf] = 0.f; }
#pragma unroll
    for (int nt = 0; nt < 4; nt++)
#pragma unroll
        for (int c = 0; c < 4; c++) o[nt][c] = 0.f;

    for (int k0 = 0; k0 < SS; k0 += FN) {
        __syncthreads();
        for (int f = t; f < FN*8; f += 128) {
            int r = f >> 3, c4 = (f & 7) * 4;
            int gr = k0 + r;
            float4 kv = make_float4(0.f,0.f,0.f,0.f), vv = make_float4(0.f,0.f,0.f,0.f);
            if (gr < SS) {
                const float* base = g_qkv0 + (size_t)gr*768 + h*HDIM + c4;
                kv = *(const float4*)(base + DD);
                vv = *(const float4*)(base + 2*DD);
                int sl = didx[gr];
                if (sl >= 0) {
                    const float* dbase = g_dq + (size_t)sl*768 + h*HDIM + c4;
                    float4 dk = *(const float4*)(dbase + DD);
                    float4 dv = *(const float4*)(dbase + 2*DD);
                    kv.x += dk.x; kv.y += dk.y; kv.z += dk.z; kv.w += dk.w;
                    vv.x += dv.x; vv.y += dv.y; vv.z += dv.z; vv.w += dv.w;
                }
            }
            __half h0 = __float2half_rn(kv.x), h1 = __float2half_rn(kv.y);
            __half h2 = __float2half_rn(kv.z), h3 = __float2half_rn(kv.w);
            Kh2[r][c4/2  ] = __halves2half2(h0, h1);
            Kh2[r][c4/2+1] = __halves2half2(h2, h3);
            Kl2[r][c4/2  ] = __halves2half2(__float2half_rn(kv.x - __half2float(h0)),
                                            __float2half_rn(kv.y - __half2float(h1)));
            Kl2[r][c4/2+1] = __halves2half2(__float2half_rn(kv.z - __half2float(h2)),
                                            __float2half_rn(kv.w - __half2float(h3)));
            Vst[c4+0][r] = __float2half_rn(vv.x);
            Vst[c4+1][r] = __float2half_rn(vv.y);
            Vst[c4+2][r] = __float2half_rn(vv.z);
            Vst[c4+3][r] = __float2half_rn(vv.w);
        }
        __syncthreads();

        float c[8][4];
#pragma unroll
        for (int nt = 0; nt < 8; nt++) {
            c[nt][0] = c[nt][1] = c[nt][2] = c[nt][3] = 0.f;
            int kr = nt*8 + l4;
#pragma unroll
            for (int ks = 0; ks < 2; ks++) {
                int kk2 = ks*8;
                uint32_t bh0 = *(const uint32_t*)&Kh2[kr][kk2+lm  ];
                uint32_t bh1 = *(const uint32_t*)&Kh2[kr][kk2+lm+4];
                uint32_t bl0 = *(const uint32_t*)&Kl2[kr][kk2+lm  ];
                uint32_t bl1 = *(const uint32_t*)&Kl2[kr][kk2+lm+4];
                mma_f16(c[nt], aqh[ks], bl0, bl1);   // Qh*Kl
                mma_f16(c[nt], aql[ks], bh0, bh1);   // Ql*Kh
                mma_f16(c[nt], aqh[ks], bh0, bh1);   // Qh*Kh (dominant last)
            }
        }
        if (k0 + FN > SS) {
#pragma unroll
            for (int nt = 0; nt < 8; nt++) {
                int j0 = k0 + nt*8 + lm*2;
                if (j0 >= SS) { c[nt][0] = c[nt][1] = c[nt][2] = c[nt][3] = -1e30f; }
            }
        }
#pragma unroll
        for (int hf = 0; hf < 2; hf++) {
            float rm = -INFINITY;
#pragma unroll
            for (int nt = 0; nt < 8; nt++)
                rm = fmaxf(rm, fmaxf(c[nt][2*hf], c[nt][2*hf+1]));
            rm = fmaxf(rm, __shfl_xor_sync(0xffffffffu, rm, 1));
            rm = fmaxf(rm, __shfl_xor_sync(0xffffffffu, rm, 2));
            float mn = fmaxf(m_i[hf], rm);
            float alpha = exp2f(m_i[hf] - mn);
            float rs = 0.f;
#pragma unroll
            for (int nt = 0; nt < 8; nt++) {
                float p0 = exp2f(c[nt][2*hf]   - mn);
                float p1 = exp2f(c[nt][2*hf+1] - mn);
                c[nt][2*hf] = p0; c[nt][2*hf+1] = p1;
                rs += p0 + p1;
            }
            rs += __shfl_xor_sync(0xffffffffu, rs, 1);
            rs += __shfl_xor_sync(0xffffffffu, rs, 2);
            l_i[hf] = l_i[hf]*alpha + rs;
            m_i[hf] = mn;
#pragma unroll
            for (int nt = 0; nt < 4; nt++) {
                o[nt][2*hf]   *= alpha;
                o[nt][2*hf+1] *= alpha;
            }
        }
#pragma unroll
        for (int nt = 0; nt < 8; nt++) {
            Ps2[r0+l4  ][nt*4+lm] = __floats2half2_rn(c[nt][0], c[nt][1]);
            Ps2[r0+l4+8][nt*4+lm] = __floats2half2_rn(c[nt][2], c[nt][3]);
        }
        __syncwarp();
#pragma unroll
        for (int ks = 0; ks < 4; ks++) {
            int kk2 = ks*8;
            int kk  = ks*16;
            uint32_t a[4];
            a[0] = *(const uint32_t*)&Ps2[r0+l4  ][kk2+lm  ];
            a[1] = *(const uint32_t*)&Ps2[r0+l4+8][kk2+lm  ];
            a[2] = *(const uint32_t*)&Ps2[r0+l4  ][kk2+lm+4];
            a[3] = *(const uint32_t*)&Ps2[r0+l4+8][kk2+lm+4];
#pragma unroll
            for (int nt = 0; nt < 4; nt++) {
                uint32_t b0 = *(const uint32_t*)&Vst[nt*8+l4][kk + 2*lm    ];
                uint32_t b1 = *(const uint32_t*)&Vst[nt*8+l4][kk + 2*lm + 8];
                mma_f16(o[nt], a, b0, b1);
            }
        }
        __syncwarp();
    }

#pragma unroll
    for (int hf = 0; hf < 2; hf++) {
        int gr = q0 + r0 + l4 + hf*8;
        if (gr < SS) {
            float inv = 1.f / l_i[hf];
#pragma unroll
            for (int nt = 0; nt < 4; nt++) {
                float2 v = make_float2(o[nt][2*hf]*inv, o[nt][2*hf+1]*inv);
                *(float2*)&g_ctx[(size_t)(b*SS+gr)*DD + h*HDIM + nt*8 + lm*2] = v;
            }
        }
    }
}

// ---------------- pool stage 1: partial sums over 98-row stripes ----------------
__global__ void k_pool1() {
    int b = blockIdx.x, ch = blockIdx.y, t = threadIdx.x;
    float s = 0.f;
    const float* base = g_ctx + ((size_t)b*SS + ch*98)*DD + t;
#pragma unroll 7
    for (int si = 0; si < 98; si++) s += base[(size_t)si*DD];
    g_part[((size_t)b*8 + ch)*DD + t] = s;
}

// ---------------- pool stage 2: fold partials + out-proj + state reset ----------------
__global__ void k_pool2(const float* __restrict__ Wo, const float* __restrict__ bo,
                        float* __restrict__ out) {
    __shared__ float mean[DD];
    int b = blockIdx.x, t = threadIdx.x;
    int gid = b*256 + t;
    if (gid < 2048) g_hist1[gid] = 0;
    else if (gid < 4096) g_hist2[gid - 2048] = 0;
    else if (gid < 5120) g_hist3[gid - 4096] = 0;
    else if (gid == 5120) g_nact = 0;
    else if (gid == 5121) g_ncand = 0;

    float s = 0.f;
    const float* pb = g_part + (size_t)b*8*DD + t;
#pragma unroll
    for (int ch = 0; ch < 8; ch++) s += pb[ch*DD];
    mean[t] = s * (1.f / (float)SS);
    __syncthreads();
    float acc = bo[t];
    const float* wrow = Wo + t*DD;
#pragma unroll 8
    for (int d = 0; d < DD; d++) acc += mean[d]*wrow[d];
    out[b*DD + t] = acc;
}

// ---------------- launch ----------------
extern "C" void kernel_launch(void* const* d_in, const int* in_sizes, int n_in,
                              void* d_out, int out_size) {
    const float* x    = (const float*)d_in[0];
    const float* cw   = (const float*)d_in[1];
    const float* emb  = (const float*)d_in[2];
    const float* ipw  = (const float*)d_in[3];
    const float* ipb  = (const float*)d_in[4];
    const float* opw  = (const float*)d_in[5];
    const float* opb  = (const float*)d_in[6];
    float* out = (float*)d_out;
    int full_out = (out_size >= OUT_FULL) ? 1 : 0;

    k_conv_pe<<<1040, 256>>>(x, cw);
    k_hist2<<<256, 256>>>();
    k_hist3<<<16, 256>>>();
    k_sparse<<<(BB*SS + 255)/256, 256>>>(emb, out, full_out);
    k_qkvdelta<<<dim3(26, 12), 256>>>(ipw, ipb);
    k_flash<<<dim3((SS + FM - 1)/FM, NHH, BB), 128>>>();
    k_pool1<<<dim3(BB, 8), 256>>>();
    k_pool2<<<BB, 256>>>(opw, opb, out);
}

// round 17
// speedup vs baseline: 1.0453x; 1.0258x over previous
#include <cuda_runtime.h>
#include <cuda_fp16.h>
#include <math.h>
#include <stdint.h>

// ---------------- problem constants ----------------
#define BB   32
#define HH   28
#define WW   28
#define C1   64
#define DD   256
#define NHH  8
#define HDIM 32
#define SS   784            // HH*WW
#define TOT  (BB*C1*SS)     // 1,605,632
#define KSEL 803            // ceil(0.0005 * TOT)
#define MAXACT 832
#define NTILE 13            // q-tiles per (b,h)

#define SW_OFF   8192
#define SW_SIZE  (BB*SS*C1)
#define IDX_OFF  (SW_OFF + SW_SIZE)
#define OUT_FULL (IDX_OFF + BB*SS*2)

#define FSCALE (0.17677669529663689f * 1.4426950408889634f)  // 1/sqrt(32)*log2(e)

// ---------------- device scratch ----------------
__device__ __align__(16) float g_A[TOT];                 // conv output, layout [b][c][s]
__device__ __align__(16) float g_pe[SS*DD];
__device__ __align__(16) float g_qkv0[SS*3*DD];          // PE @ Wqkv^T + b (batch-invariant)
__device__ __align__(16) float g_dq[MAXACT*3*DD];        // sparse qkv deltas (compact)
__device__ __align__(16) float g_U[MAXACT*DD];
__device__ __align__(16) float g_tsum[BB*NTILE*DD];      // per-tile ctx column sums
__device__ __align__(16) unsigned g_cand[TOT];           // level-1 prefix candidates
__device__ int      g_didx[BB*SS];
__device__ unsigned g_hist1[2048];
__device__ unsigned g_hist2[2048];
__device__ unsigned g_hist3[1024];
__device__ int      g_nact;
__device__ int      g_ncand;

__device__ __forceinline__ void mma_f16(float c[4], const uint32_t a[4],
                                        uint32_t b0, uint32_t b1) {
    asm volatile("mma.sync.aligned.m16n8k16.row.col.f32.f16.f16.f32 "
                 "{%0,%1,%2,%3}, {%4,%5,%6,%7}, {%8,%9}, {%0,%1,%2,%3};"
                 : "+f"(c[0]), "+f"(c[1]), "+f"(c[2]), "+f"(c[3])
                 : "r"(a[0]), "r"(a[1]), "r"(a[2]), "r"(a[3]), "r"(b0), "r"(b1));
}

// Block-local radix scan over a completed global histogram.
__device__ __forceinline__ bool scan_bins(const unsigned* hist, int nbins, unsigned k,
                                          unsigned* part, unsigned* suf,
                                          unsigned& sel_out, unsigned& krem_out) {
    int t = threadIdx.x;
    int chunk = nbins / 256;
    unsigned loc[8];
    unsigned psum = 0;
    for (int i = 0; i < chunk; i++) { loc[i] = hist[t*chunk + i]; psum += loc[i]; }
    part[t] = psum; suf[t] = psum;
    __syncthreads();
    for (int off = 1; off < 256; off <<= 1) {
        unsigned v = suf[t];
        if (t + off < 256) v += suf[t + off];
        __syncthreads();
        suf[t] = v;
        __syncthreads();
    }
    unsigned total = suf[0];
    unsigned above = suf[t] - part[t];
    __syncthreads();
    if (total < k) return false;
    if (above < k && suf[t] >= k) {
        unsigned cum = above;
        for (int i = chunk - 1; i >= 0; i--) {
            cum += loc[i];
            if (cum >= k) {
                part[0] = (unsigned)(t*chunk + i);
                part[1] = k - (cum - loc[i]);
                break;
            }
        }
    }
    __syncthreads();
    sel_out = part[0]; krem_out = part[1];
    __syncthreads();
    return true;
}

// ---------------- fused conv(9x9)+relu+hist1 (A stored [b][c][s]) | PE ----------------
__global__ void k_conv_pe(const float* __restrict__ x, const float* __restrict__ cw) {
    int blk = blockIdx.x;
    int t = threadIdx.x;
    if (blk >= 256) {
        int s = blk - 256;
        int h = s / WW, w = s % WW;
        int i2 = t & ~1;
        float div = expf((float)i2 * (-logf(10000.0f) / (float)DD));
        float val = (t & 1) ? cosf((float)w * div) : sinf((float)h * div);
        g_pe[s * DD + t] = val;
        return;
    }
    __shared__ float xs[36][36];
    __shared__ float ws[8][81];
    __shared__ unsigned sh[2048];
    int b = blk >> 3, cg = blk & 7;
    for (int e = t; e < 36*36; e += 256) {
        int r = e / 36, c = e % 36;
        int hh = r - 4, ww = c - 4;
        xs[r][c] = (hh >= 0 && hh < HH && ww >= 0 && ww < WW) ? x[b*SS + hh*WW + ww] : 0.f;
    }
    for (int e = t; e < 8*81; e += 256) {
        int c8 = e / 81, k = e % 81;
        ws[c8][k] = cw[(cg*8 + c8)*81 + k];
    }
    for (int i = t; i < 2048; i += 256) sh[i] = 0;
    __syncthreads();
    for (int c8 = 0; c8 < 8; c8++) {
        for (int p = t; p < SS; p += 256) {
            int hh = p / WW, ww = p % WW;
            float acc = 0.f;
#pragma unroll
            for (int ky = 0; ky < 9; ky++)
#pragma unroll
                for (int kx = 0; kx < 9; kx++)
                    acc += xs[hh+ky][ww+kx] * ws[c8][ky*9 + kx];
            acc = fmaxf(acc, 0.f);
            g_A[((b*C1) + cg*8 + c8)*SS + p] = acc;
            unsigned u = __float_as_uint(acc);
            if (u) atomicAdd(&sh[u >> 21], 1u);
        }
    }
    __syncthreads();
    for (int i = t; i < 2048; i += 256) { unsigned v = sh[i]; if (v) atomicAdd(&g_hist1[i], v); }
}

// ---------------- hist2: scan1 prologue + level-2 histogram + candidate compaction ----------------
__global__ void k_hist2() {
    __shared__ unsigned sh[2048];
    __shared__ unsigned sp[256], ssu[256];
    int t = threadIdx.x;
    unsigned sel1, krem1;
    if (!scan_bins(g_hist1, 2048, KSEL, sp, ssu, sel1, krem1)) return;
    for (int i = t; i < 2048; i += 256) sh[i] = 0;
    __syncthreads();
    const uint4* a4 = (const uint4*)g_A;
    for (int idx = blockIdx.x*256 + t; idx < TOT/4; idx += gridDim.x*256) {
        uint4 u4 = a4[idx];
        unsigned uu[4] = {u4.x, u4.y, u4.z, u4.w};
#pragma unroll
        for (int j = 0; j < 4; j++) {
            unsigned u = uu[j];
            if (u && (u >> 21) == sel1) {
                atomicAdd(&sh[(u >> 10) & 0x7FF], 1u);
                int pos = atomicAdd(&g_ncand, 1);
                g_cand[pos] = u;
            }
        }
    }
    __syncthreads();
    for (int i = t; i < 2048; i += 256) { unsigned v = sh[i]; if (v) atomicAdd(&g_hist2[i], v); }
}

// ---------------- hist3: scan1+scan2 prologue + level-3 histogram over candidates ----------------
__global__ void k_hist3() {
    __shared__ unsigned sh[1024];
    __shared__ unsigned sp[256], ssu[256];
    int t = threadIdx.x;
    unsigned sel1, krem1, sel2, krem2;
    if (!scan_bins(g_hist1, 2048, KSEL, sp, ssu, sel1, krem1)) return;
    if (!scan_bins(g_hist2, 2048, krem1, sp, ssu, sel2, krem2)) return;
    int n = g_ncand;
    for (int i = t; i < 1024; i += 256) sh[i] = 0;
    __syncthreads();
    for (int i = blockIdx.x*256 + t; i < n; i += gridDim.x*256) {
        unsigned u = g_cand[i];
        if (((u >> 10) & 0x7FF) == sel2) atomicAdd(&sh[u & 0x3FF], 1u);
    }
    __syncthreads();
    for (int i = t; i < 1024; i += 256) { unsigned v = sh[i]; if (v) atomicAdd(&g_hist3[i], v); }
}

// ---------------- sparse: 3-scan prologue -> thresh; vectorized writes ----------------
__global__ void k_sparse(const float* __restrict__ emb, float* __restrict__ out, int full_out) {
    __shared__ unsigned sp[256], ssu[256];
    unsigned sel1, krem1, sel2, krem2, sel3, krem3;
    float thr = 0.f;
    if (scan_bins(g_hist1, 2048, KSEL, sp, ssu, sel1, krem1) &&
        scan_bins(g_hist2, 2048, krem1, sp, ssu, sel2, krem2) &&
        scan_bins(g_hist3, 1024, krem2, sp, ssu, sel3, krem3)) {
        unsigned prefix2 = (sel1 << 11) | sel2;
        thr = __uint_as_float((prefix2 << 10) | sel3);
    }
    int p = blockIdx.x*256 + threadIdx.x;
    if (p >= BB*SS) return;
    int b = p / SS, s = p % SS;
    float m1 = -INFINITY, m2 = -INFINITY;
    int i1 = 0, i2 = 0, cnt = 0;
    const float* ap = g_A + (size_t)b*C1*SS + s;
#pragma unroll 16
    for (int c = 0; c < C1; c++) {
        float a = ap[c*SS];
        float v = (a >= thr) ? a : 0.f;
        if (v > 0.f) cnt++;
        if (v > m1) { m2 = m1; i2 = i1; m1 = v; i1 = c; }
        else if (v > m2) { m2 = v; i2 = c; }
    }
    float wA = 0.f, wB = 0.f;
    if (cnt == 1) wA = 1.f;
    else if (cnt >= 2) {
        float e2 = expf(m2 - m1);
        float z = 1.f + e2;
        wA = 1.f / z; wB = e2 / z;
    }
    if (full_out) {
        float* sw = out + SW_OFF + (size_t)p*C1;
        float4 z4 = make_float4(0.f, 0.f, 0.f, 0.f);
#pragma unroll
        for (int c4 = 0; c4 < C1; c4 += 4) {
            float4 v4 = z4;
            if (i1 >= c4 && i1 < c4+4) (&v4.x)[i1 - c4] = wA;
            if (i2 >= c4 && i2 < c4+4) (&v4.x)[i2 - c4] = wB;
            *(float4*)&sw[c4] = v4;
        }
        out[IDX_OFF + p*2]     = (float)i1;
        out[IDX_OFF + p*2 + 1] = (float)i2;
    }
    int slotw = -1;
    if (cnt > 0) {
        int slot = atomicAdd(&g_nact, 1);
        if (slot < MAXACT) {
            slotw = slot;
            float w2v = (cnt >= 2) ? wB : 0.f;
            float* up = g_U + (size_t)slot*DD;
            const float* e1p = emb + i1*DD;
            const float* e2p = emb + i2*DD;
#pragma unroll 4
            for (int d4 = 0; d4 < DD; d4 += 4) {
                float4 e1 = *(const float4*)&e1p[d4];
                float4 e2 = *(const float4*)&e2p[d4];
                float4 u4;
                u4.x = wA*e1.x + w2v*e2.x;
                u4.y = wA*e1.y + w2v*e2.y;
                u4.z = wA*e1.z + w2v*e2.z;
                u4.w = wA*e1.w + w2v*e2.w;
                *(float4*)&up[d4] = u4;
            }
        }
    }
    g_didx[p] = slotw;
}

// ---------------- fused qkv0 (x<13) + delta (x>=13) ----------------
__global__ void k_qkvdelta(const float* __restrict__ Wq, const float* __restrict__ bias) {
    __shared__ float As[16][68];
    __shared__ float Bs[16][68];
    int tx = threadIdx.x % 16, ty = threadIdx.x / 16;
    int bx = blockIdx.x;
    int is_delta = (bx >= 13);
    int m0 = (is_delta ? (bx - 13) : bx) * 64;
    int n0 = blockIdx.y*64;
    int mlim;
    const float* Asrc;
    if (is_delta) {
        int nact = g_nact; if (nact > MAXACT) nact = MAXACT;
        if (m0 >= nact) return;
        mlim = nact;
        Asrc = g_U;
    } else {
        mlim = SS;
        Asrc = g_pe;
    }
    float acc[4][4] = {};
    int lr = threadIdx.x / 4;
    int lk = (threadIdx.x % 4) * 4;
    for (int k0 = 0; k0 < DD; k0 += 16) {
        float4 av = (m0 + lr < mlim) ? *(const float4*)&Asrc[(size_t)(m0+lr)*DD + k0 + lk] : make_float4(0,0,0,0);
        float4 bv = *(const float4*)&Wq[(n0+lr)*DD + k0 + lk];
        __syncthreads();
        As[lk+0][lr] = av.x; As[lk+1][lr] = av.y; As[lk+2][lr] = av.z; As[lk+3][lr] = av.w;
        Bs[lk+0][lr] = bv.x; Bs[lk+1][lr] = bv.y; Bs[lk+2][lr] = bv.z; Bs[lk+3][lr] = bv.w;
        __syncthreads();
#pragma unroll
        for (int kk = 0; kk < 16; kk++) {
            float4 a4 = *(const float4*)&As[kk][ty*4];
            float4 b4 = *(const float4*)&Bs[kk][tx*4];
            float sa[4] = {a4.x, a4.y, a4.z, a4.w};
            float sb[4] = {b4.x, b4.y, b4.z, b4.w};
#pragma unroll
            for (int i = 0; i < 4; i++)
#pragma unroll
                for (int j = 0; j < 4; j++)
                    acc[i][j] += sa[i]*sb[j];
        }
    }
#pragma unroll
    for (int i = 0; i < 4; i++) {
        int m = m0 + ty*4 + i;
        if (m < mlim) {
            if (is_delta) {
                float* dst = g_dq + (size_t)m*768 + n0 + tx*4;
#pragma unroll
                for (int j = 0; j < 4; j++) dst[j] = acc[i][j];
            } else {
#pragma unroll
                for (int j = 0; j < 4; j++) {
                    int n = n0 + tx*4 + j;
                    g_qkv0[m*768 + n] = acc[i][j] + bias[n];
                }
            }
        }
    }
}

// ---------------- tensor-core flash attention (fp16, FM=64) + fused tile pooling ----------------
#define FM 64
#define FN 64
__global__ __launch_bounds__(128, 5) void k_flash() {
    __shared__ __align__(16) float   Qs[FM][36];     // fp32 Q staging
    __shared__ __align__(16) __half2 Ps2[FM][36];    // P tiles (per-warp rows)
    __shared__ __align__(16) __half2 Kh2[FN][20];    // K hi
    __shared__ __align__(16) __half2 Kl2[FN][20];    // K lo
    __shared__ __align__(16) __half  Vst[32][72];    // V^T [dim][key]
    __shared__ __align__(16) float   sums[4][32];    // per-warp pooled column sums
    int b = blockIdx.z, h = blockIdx.y;
    int q0 = blockIdx.x * FM;
    int t = threadIdx.x;
    int w = t >> 5, lane = t & 31;
    int l4 = lane >> 2, lm = lane & 3;

    const int* didx = g_didx + b*SS;

    for (int f = t; f < FM*8; f += 128) {
        int r = f >> 3, c4 = (f & 7) * 4;
        int gr = q0 + r;
        float4 v = make_float4(0.f,0.f,0.f,0.f);
        if (gr < SS) {
            v = *(const float4*)(g_qkv0 + (size_t)gr*768 + h*HDIM + c4);
            int sl = didx[gr];
            if (sl >= 0) {
                float4 d = *(const float4*)(g_dq + (size_t)sl*768 + h*HDIM + c4);
                v.x += d.x; v.y += d.y; v.z += d.z; v.w += d.w;
            }
        }
        Qs[r][c4+0] = v.x*FSCALE; Qs[r][c4+1] = v.y*FSCALE;
        Qs[r][c4+2] = v.z*FSCALE; Qs[r][c4+3] = v.w*FSCALE;
    }
    __syncthreads();

    int r0 = w * 16;
    uint32_t aqh[2][4], aql[2][4];
#pragma unroll
    for (int ks = 0; ks < 2; ks++) {
        int kk = ks*16;
        float p0[4], p1[4];
        p0[0] = Qs[r0+l4  ][kk+2*lm  ];  p1[0] = Qs[r0+l4  ][kk+2*lm+1];
        p0[1] = Qs[r0+l4+8][kk+2*lm  ];  p1[1] = Qs[r0+l4+8][kk+2*lm+1];
        p0[2] = Qs[r0+l4  ][kk+2*lm+8];  p1[2] = Qs[r0+l4  ][kk+2*lm+9];
        p0[3] = Qs[r0+l4+8][kk+2*lm+8];  p1[3] = Qs[r0+l4+8][kk+2*lm+9];
#pragma unroll
        for (int j = 0; j < 4; j++) {
            __half h0 = __float2half_rn(p0[j]);
            __half h1 = __float2half_rn(p1[j]);
            __half l0 = __float2half_rn(p0[j] - __half2float(h0));
            __half l1 = __float2half_rn(p1[j] - __half2float(h1));
            __half2 hh = __halves2half2(h0, h1);
            __half2 ll = __halves2half2(l0, l1);
            aqh[ks][j] = *(uint32_t*)&hh;
            aql[ks][j] = *(uint32_t*)&ll;
        }
    }

    float m_i[2], l_i[2], o[4][4];
#pragma unroll
    for (int hf = 0; hf < 2; hf++) { m_i[hf] = -INFINITY; l_i[hf] = 0.f; }
#pragma unroll
    for (int nt = 0; nt < 4; nt++)
#pragma unroll
        for (int c = 0; c < 4; c++) o[nt][c] = 0.f;

    for (int k0 = 0; k0 < SS; k0 += FN) {
        __syncthreads();
        for (int f = t; f < FN*8; f += 128) {
            int r = f >> 3, c4 = (f & 7) * 4;
            int gr = k0 + r;
            float4 kv = make_float4(0.f,0.f,0.f,0.f), vv = make_float4(0.f,0.f,0.f,0.f);
            if (gr < SS) {
                const float* base = g_qkv0 + (size_t)gr*768 + h*HDIM + c4;
                kv = *(const float4*)(base + DD);
                vv = *(const float4*)(base + 2*DD);
                int sl = didx[gr];
                if (sl >= 0) {
                    const float* dbase = g_dq + (size_t)sl*768 + h*HDIM + c4;
                    float4 dk = *(const float4*)(dbase + DD);
                    float4 dv = *(const float4*)(dbase + 2*DD);
                    kv.x += dk.x; kv.y += dk.y; kv.z += dk.z; kv.w += dk.w;
                    vv.x += dv.x; vv.y += dv.y; vv.z += dv.z; vv.w += dv.w;
                }
            }
            __half h0 = __float2half_rn(kv.x), h1 = __float2half_rn(kv.y);
            __half h2 = __float2half_rn(kv.z), h3 = __float2half_rn(kv.w);
            Kh2[r][c4/2  ] = __halves2half2(h0, h1);
            Kh2[r][c4/2+1] = __halves2half2(h2, h3);
            Kl2[r][c4/2  ] = __halves2half2(__float2half_rn(kv.x - __half2float(h0)),
                                            __float2half_rn(kv.y - __half2float(h1)));
            Kl2[r][c4/2+1] = __halves2half2(__float2half_rn(kv.z - __half2float(h2)),
                                            __float2half_rn(kv.w - __half2float(h3)));
            Vst[c4+0][r] = __float2half_rn(vv.x);
            Vst[c4+1][r] = __float2half_rn(vv.y);
            Vst[c4+2][r] = __float2half_rn(vv.z);
            Vst[c4+3][r] = __float2half_rn(vv.w);
        }
        __syncthreads();

        float c[8][4];
#pragma unroll
        for (int nt = 0; nt < 8; nt++) {
            c[nt][0] = c[nt][1] = c[nt][2] = c[nt][3] = 0.f;
            int kr = nt*8 + l4;
#pragma unroll
            for (int ks = 0; ks < 2; ks++) {
                int kk2 = ks*8;
                uint32_t bh0 = *(const uint32_t*)&Kh2[kr][kk2+lm  ];
                uint32_t bh1 = *(const uint32_t*)&Kh2[kr][kk2+lm+4];
                uint32_t bl0 = *(const uint32_t*)&Kl2[kr][kk2+lm  ];
                uint32_t bl1 = *(const uint32_t*)&Kl2[kr][kk2+lm+4];
                mma_f16(c[nt], aqh[ks], bl0, bl1);   // Qh*Kl
                mma_f16(c[nt], aql[ks], bh0, bh1);   // Ql*Kh
                mma_f16(c[nt], aqh[ks], bh0, bh1);   // Qh*Kh (dominant last)
            }
        }
        if (k0 + FN > SS) {
#pragma unroll
            for (int nt = 0; nt < 8; nt++) {
                int j0 = k0 + nt*8 + lm*2;
                if (j0 >= SS) { c[nt][0] = c[nt][1] = c[nt][2] = c[nt][3] = -1e30f; }
            }
        }
#pragma unroll
        for (int hf = 0; hf < 2; hf++) {
            float rm = -INFINITY;
#pragma unroll
            for (int nt = 0; nt < 8; nt++)
                rm = fmaxf(rm, fmaxf(c[nt][2*hf], c[nt][2*hf+1]));
            rm = fmaxf(rm, __shfl_xor_sync(0xffffffffu, rm, 1));
            rm = fmaxf(rm, __shfl_xor_sync(0xffffffffu, rm, 2));
            float mn = fmaxf(m_i[hf], rm);
            float alpha = exp2f(m_i[hf] - mn);
            float rs = 0.f;
#pragma unroll
            for (int nt = 0; nt < 8; nt++) {
                float p0 = exp2f(c[nt][2*hf]   - mn);
                float p1 = exp2f(c[nt][2*hf+1] - mn);
                c[nt][2*hf] = p0; c[nt][2*hf+1] = p1;
                rs += p0 + p1;
            }
            rs += __shfl_xor_sync(0xffffffffu, rs, 1);
            rs += __shfl_xor_sync(0xffffffffu, rs, 2);
            l_i[hf] = l_i[hf]*alpha + rs;
            m_i[hf] = mn;
#pragma unroll
            for (int nt = 0; nt < 4; nt++) {
                o[nt][2*hf]   *= alpha;
                o[nt][2*hf+1] *= alpha;
            }
        }
#pragma unroll
        for (int nt = 0; nt < 8; nt++) {
            Ps2[r0+l4  ][nt*4+lm] = __floats2half2_rn(c[nt][0], c[nt][1]);
            Ps2[r0+l4+8][nt*4+lm] = __floats2half2_rn(c[nt][2], c[nt][3]);
        }
        __syncwarp();
#pragma unroll
        for (int ks = 0; ks < 4; ks++) {
            int kk2 = ks*8;
            int kk  = ks*16;
            uint32_t a[4];
            a[0] = *(const uint32_t*)&Ps2[r0+l4  ][kk2+lm  ];
            a[1] = *(const uint32_t*)&Ps2[r0+l4+8][kk2+lm  ];
            a[2] = *(const uint32_t*)&Ps2[r0+l4  ][kk2+lm+4];
            a[3] = *(const uint32_t*)&Ps2[r0+l4+8][kk2+lm+4];
#pragma unroll
            for (int nt = 0; nt < 4; nt++) {
                uint32_t b0 = *(const uint32_t*)&Vst[nt*8+l4][kk + 2*lm    ];
                uint32_t b1 = *(const uint32_t*)&Vst[nt*8+l4][kk + 2*lm + 8];
                mma_f16(o[nt], a, b0, b1);
            }
        }
        __syncwarp();
    }

    // fused pooled epilogue: deterministic per-tile column sums (no g_ctx)
    float inv0 = 1.f / l_i[0], inv1 = 1.f / l_i[1];
    int gr0 = q0 + r0 + l4;
    bool v0 = gr0 < SS, v1 = (gr0 + 8) < SS;
#pragma unroll
    for (int nt = 0; nt < 4; nt++) {
#pragma unroll
        for (int sub = 0; sub < 2; sub++) {
            float val = 0.f;
            if (v0) val += o[nt][sub]     * inv0;
            if (v1) val += o[nt][2 + sub] * inv1;
            val += __shfl_xor_sync(0xffffffffu, val, 4);
            val += __shfl_xor_sync(0xffffffffu, val, 8);
            val += __shfl_xor_sync(0xffffffffu, val, 16);
            if (l4 == 0) sums[w][nt*8 + lm*2 + sub] = val;
        }
    }
    __syncthreads();
    if (t < 32) {
        float s = sums[0][t] + sums[1][t] + sums[2][t] + sums[3][t];
        g_tsum[((size_t)(b*NTILE + blockIdx.x))*DD + h*HDIM + t] = s;
    }
}

// ---------------- pool: fold tile sums + out-proj + state reset ----------------
__global__ void k_pool2(const float* __restrict__ Wo, const float* __restrict__ bo,
                        float* __restrict__ out) {
    __shared__ float mean[DD];
    int b = blockIdx.x, t = threadIdx.x;
    int gid = b*256 + t;
    if (gid < 2048) g_hist1[gid] = 0;
    else if (gid < 4096) g_hist2[gid - 2048] = 0;
    else if (gid < 5120) g_hist3[gid - 4096] = 0;
    else if (gid == 5120) g_nact = 0;
    else if (gid == 5121) g_ncand = 0;

    float s = 0.f;
    const float* tb = g_tsum + (size_t)b*NTILE*DD + t;
#pragma unroll
    for (int x = 0; x < NTILE; x++) s += tb[x*DD];
    mean[t] = s * (1.f / (float)SS);
    __syncthreads();
    float acc = bo[t];
    const float* wrow = Wo + t*DD;
#pragma unroll 8
    for (int d = 0; d < DD; d++) acc += mean[d]*wrow[d];
    out[b*DD + t] = acc;
}

// ---------------- launch ----------------
extern "C" void kernel_launch(void* const* d_in, const int* in_sizes, int n_in,
                              void* d_out, int out_size) {
    const float* x    = (const float*)d_in[0];
    const float* cw   = (const float*)d_in[1];
    const float* emb  = (const float*)d_in[2];
    const float* ipw  = (const float*)d_in[3];
    const float* ipb  = (const float*)d_in[4];
    const float* opw  = (const float*)d_in[5];
    const float* opb  = (const float*)d_in[6];
    float* out = (float*)d_out;
    int full_out = (out_size >= OUT_FULL) ? 1 : 0;

    k_conv_pe<<<1040, 256>>>(x, cw);
    k_hist2<<<256, 256>>>();
    k_hist3<<<16, 256>>>();
    k_sparse<<<(BB*SS + 255)/256, 256>>>(emb, out, full_out);
    k_qkvdelta<<<dim3(26, 12), 256>>>(ipw, ipb);
    k_flash<<<dim3(NTILE, NHH, BB), 128>>>();
    k_pool2<<<BB, 256>>>(opw, opb, out);
}